// round 6
// baseline (speedup 1.0000x reference)
#include <cuda_runtime.h>
#include <cuda_fp16.h>
#include <cstddef>

#define NB 2
#define NC 128
#define NE 60000
#define TR_BLOCKS (2 * NB * 2 * (NE / 32))          // 15000 transpose tiles
#define W_WARPS   (2 * NC * 15 + 3)
#define W_BLOCKS  ((W_WARPS + 7) / 8)
#define GROUPS2   (NB * NE / 2)                      // 60000 2-edge groups

// Transposed inputs in fp16: [tensor][b*E+e][c] (256B per edge row)
__device__ __half g_xth[2][(size_t)NB * NE * NC];
// Effective fused weights: [branch][c][s*3+k] padded to 16
__device__ float g_V[2][NC][16];
__device__ float g_cb[3];

// ---------------------------------------------------------------------------
// Kernel 1 (fused): blocks < TR_BLOCKS transpose x->fp16 (64c x 32e tiles);
// the remaining blocks fold the weights.
// ---------------------------------------------------------------------------
__global__ void __launch_bounds__(256)
prep_kernel(const float* __restrict__ x0, const float* __restrict__ x1,
    const float* __restrict__ Wa_local, const float* __restrict__ ba_local,
    const float* __restrict__ Wb_local, const float* __restrict__ bb_local,
    const float* __restrict__ Wa_tri,   const float* __restrict__ ba_tri,
    const float* __restrict__ Wb_tri,   const float* __restrict__ bb_tri,
    const float* __restrict__ Wa_fuse,  const float* __restrict__ ba_fuse,
    const float* __restrict__ Wb_fuse,  const float* __restrict__ bb_fuse)
{
    if (blockIdx.x < TR_BLOCKS) {
        __shared__ __half tile[32][66];   // [e_local][c_local], stride 66 halves
        int bx = blockIdx.x;
        const int eb = bx % (NE / 32);  bx /= (NE / 32);
        const int ch = bx & 1;          bx >>= 1;
        const int b  = bx & 1;
        const int tensor = bx >> 1;
        const float* __restrict__ src = tensor ? x1 : x0;
        const int e0 = eb * 32, c0 = ch * 64;
        const int tx = threadIdx.x & 31;
        const int ty = threadIdx.x >> 5;

#pragma unroll
        for (int i = 0; i < 8; i++) {
            int cl = ty + 8 * i;
            tile[tx][cl] = __float2half_rn(
                src[((size_t)b * NC + c0 + cl) * NE + e0 + tx]);
        }
        __syncthreads();
        __half* __restrict__ dst = g_xth[tensor];
#pragma unroll
        for (int it = 0; it < 4; it++) {
            int e = ty * 4 + it;
            unsigned v = *reinterpret_cast<const unsigned*>(&tile[e][2 * tx]);
            *reinterpret_cast<unsigned*>(
                dst + ((size_t)(b * NE + e0 + e)) * NC + c0 + 2 * tx) = v;
        }
        return;
    }

    // ---- weight folding: one warp per output ----
    const int lane = threadIdx.x & 31;
    const int w = (blockIdx.x - TR_BLOCKS) * 8 + (threadIdx.x >> 5);

    if (w < 2 * NC * 15) {
        const int t   = w / (NC * 15);
        const int rem = w - t * (NC * 15);
        const int c   = rem / 15;
        const int sk  = rem - c * 15;
        const int s   = sk / 3;
        const int k   = sk - s * 3;
        const float* Wf = t ? Wb_fuse  : Wa_fuse;
        const float* Wt = t ? Wb_tri   : Wa_tri;
        const float* Wl = t ? Wb_local : Wa_local;
        float acc = 0.f;
#pragma unroll
        for (int j = 0; j < 4; j++) {
            int o = lane + 32 * j;
            acc = fmaf(Wf[k * (2 * NC) + NC + o], Wt[(o * NC + c) * 5 + s], acc);
            if (s == 0)
                acc = fmaf(Wf[k * (2 * NC) + o], Wl[o * NC + c], acc);
        }
#pragma unroll
        for (int off = 16; off; off >>= 1)
            acc += __shfl_xor_sync(0xffffffffu, acc, off);
        if (lane == 0) {
            g_V[t][c][sk] = acc;
            if (sk == 0) g_V[t][c][15] = 0.f;
        }
    } else if (w < 2 * NC * 15 + 3) {
        const int k = w - 2 * NC * 15;
        float acc = 0.f;
#pragma unroll
        for (int j = 0; j < 4; j++) {
            int o = lane + 32 * j;
            acc = fmaf(Wa_fuse[k * 2 * NC + o],      ba_local[o], acc);
            acc = fmaf(Wa_fuse[k * 2 * NC + NC + o], ba_tri[o],   acc);
            acc = fmaf(Wb_fuse[k * 2 * NC + o],      bb_local[o], acc);
            acc = fmaf(Wb_fuse[k * 2 * NC + NC + o], bb_tri[o],   acc);
        }
#pragma unroll
        for (int off = 16; off; off >>= 1)
            acc += __shfl_xor_sync(0xffffffffu, acc, off);
        if (lane == 0)
            g_cb[k] = acc + ba_fuse[k] + bb_fuse[k];
    }
}

// ---------------------------------------------------------------------------
// Kernel 2: main gather + fused dot. One warp owns a whole edge (both
// tensors); lane owns channels 4*lane..4*lane+3. Weights held as half2
// (60 regs); dot via HFMA2 (5-term fp16 chains, fp32 combine). No smem,
// no barriers — fully warp-autonomous. 2 edges per reduce round.
// ---------------------------------------------------------------------------
__device__ __forceinline__ __half2 u2h(const unsigned& u)
{
    return *reinterpret_cast<const __half2*>(&u);
}

// one tensor's contribution for one edge from 5 gathered rows
__device__ __forceinline__ void dot_tensor(
    const uint2 r0, const uint2 r1, const uint2 r2,
    const uint2 r3, const uint2 r4,
    const __half2 Va[15], const __half2 Vb[15],
    __half2& h0, __half2& h1, __half2& h2)  // per-k half2 partials (accumulated)
{
    // slot a = channels (4L,4L+1), slot b = (4L+2,4L+3)
    __half2 n1a = u2h(r1.x), n1b = u2h(r1.y);
    __half2 n2a = u2h(r2.x), n2b = u2h(r2.y);
    __half2 n3a = u2h(r3.x), n3b = u2h(r3.y);
    __half2 n4a = u2h(r4.x), n4b = u2h(r4.y);

    __half2 Ga[5], Gb[5];
    Ga[0] = u2h(r0.x);
    Gb[0] = u2h(r0.y);
    Ga[1] = __hadd2(n1a, n3a);  Gb[1] = __hadd2(n1b, n3b);
    Ga[2] = __hadd2(n2a, n4a);  Gb[2] = __hadd2(n2b, n4b);
    Ga[3] = __habs2(__hsub2(n1a, n3a));  Gb[3] = __habs2(__hsub2(n1b, n3b));
    Ga[4] = __habs2(__hsub2(n2a, n4a));  Gb[4] = __habs2(__hsub2(n2b, n4b));

    __half2 aa0 = __hmul2(Va[0], Ga[0]);
    __half2 aa1 = __hmul2(Va[1], Ga[0]);
    __half2 aa2 = __hmul2(Va[2], Ga[0]);
    __half2 ab0 = __hmul2(Vb[0], Gb[0]);
    __half2 ab1 = __hmul2(Vb[1], Gb[0]);
    __half2 ab2 = __hmul2(Vb[2], Gb[0]);
#pragma unroll
    for (int s = 1; s < 5; s++) {
        aa0 = __hfma2(Va[s * 3 + 0], Ga[s], aa0);
        aa1 = __hfma2(Va[s * 3 + 1], Ga[s], aa1);
        aa2 = __hfma2(Va[s * 3 + 2], Ga[s], aa2);
        ab0 = __hfma2(Vb[s * 3 + 0], Gb[s], ab0);
        ab1 = __hfma2(Vb[s * 3 + 1], Gb[s], ab1);
        ab2 = __hfma2(Vb[s * 3 + 2], Gb[s], ab2);
    }
    h0 = __hadd2(h0, __hadd2(aa0, ab0));
    h1 = __hadd2(h1, __hadd2(aa1, ab1));
    h2 = __hadd2(h2, __hadd2(aa2, ab2));
}

__global__ void __launch_bounds__(256, 2)
mesh_main_kernel(const int* __restrict__ gemm, float* __restrict__ out)
{
    const int lane = threadIdx.x & 31;
    const int gw   = blockIdx.x * 8 + (threadIdx.x >> 5);
    const int W    = gridDim.x * 8;

    // weights as half2: [tensor*2 + slot][15]  (60 regs)
    __half2 Vp[4][15];
#pragma unroll
    for (int t = 0; t < 2; t++)
#pragma unroll
        for (int j = 0; j < 2; j++) {
            const float* r0 = g_V[t][4 * lane + 2 * j];
            const float* r1 = g_V[t][4 * lane + 2 * j + 1];
#pragma unroll
            for (int sk = 0; sk < 15; sk++)
                Vp[t * 2 + j][sk] = __floats2half2_rn(r0[sk], r1[sk]);
        }
    float cbk = (lane < 6) ? g_cb[lane % 3] : 0.f;

    const int4* __restrict__ gi4 = reinterpret_cast<const int4*>(gemm);

    for (int g = gw; g < GROUPS2; g += W) {
        const int e0 = 2 * g;
        const int b  = (e0 >= NE) ? 1 : 0;
        const int eb = e0 - b * NE;

        const int4 ga = gi4[(size_t)b * NE + eb];
        const int4 gb = gi4[(size_t)b * NE + eb + 1];
        const __half* __restrict__ b0 = g_xth[0] + (size_t)b * NE * NC + lane * 4;
        const __half* __restrict__ b1 = g_xth[1] + (size_t)b * NE * NC + lane * 4;

        float res[6];
#pragma unroll
        for (int u = 0; u < 2; u++) {
            const int  e  = eb + u;
            const int4 gi = u ? gb : ga;

            uint2 ra0 = *reinterpret_cast<const uint2*>(b0 + (size_t)e    * NC);
            uint2 ra1 = *reinterpret_cast<const uint2*>(b0 + (size_t)gi.x * NC);
            uint2 ra2 = *reinterpret_cast<const uint2*>(b0 + (size_t)gi.y * NC);
            uint2 ra3 = *reinterpret_cast<const uint2*>(b0 + (size_t)gi.z * NC);
            uint2 ra4 = *reinterpret_cast<const uint2*>(b0 + (size_t)gi.w * NC);
            uint2 rb0 = *reinterpret_cast<const uint2*>(b1 + (size_t)e    * NC);
            uint2 rb1 = *reinterpret_cast<const uint2*>(b1 + (size_t)gi.x * NC);
            uint2 rb2 = *reinterpret_cast<const uint2*>(b1 + (size_t)gi.y * NC);
            uint2 rb3 = *reinterpret_cast<const uint2*>(b1 + (size_t)gi.z * NC);
            uint2 rb4 = *reinterpret_cast<const uint2*>(b1 + (size_t)gi.w * NC);

            __half2 h0 = __float2half2_rn(0.f);
            __half2 h1 = h0, h2 = h0;
            dot_tensor(ra0, ra1, ra2, ra3, ra4, Vp[0], Vp[1], h0, h1, h2);
            dot_tensor(rb0, rb1, rb2, rb3, rb4, Vp[2], Vp[3], h0, h1, h2);

            float2 f0 = __half22float2(h0);
            float2 f1 = __half22float2(h1);
            float2 f2 = __half22float2(h2);
            res[u * 3 + 0] = f0.x + f0.y;
            res[u * 3 + 1] = f1.x + f1.y;
            res[u * 3 + 2] = f2.x + f2.y;
        }

#pragma unroll
        for (int off = 16; off; off >>= 1)
#pragma unroll
            for (int r = 0; r < 6; r++)
                res[r] += __shfl_xor_sync(0xffffffffu, res[r], off);

        if (lane < 6) {
            const int u = lane / 3, k = lane - 3 * u;
            out[((size_t)b * 3 + k) * NE + eb + u] = res[lane] + cbk;
        }
    }
}

// ---------------------------------------------------------------------------
extern "C" void kernel_launch(void* const* d_in, const int* in_sizes, int n_in,
                              void* d_out, int out_size)
{
    const float* x_0      = (const float*)d_in[0];
    const float* x_1      = (const float*)d_in[1];
    const int*   gemm     = (const int*)  d_in[2];
    const float* Wa_local = (const float*)d_in[3];
    const float* ba_local = (const float*)d_in[4];
    const float* Wb_local = (const float*)d_in[5];
    const float* bb_local = (const float*)d_in[6];
    const float* Wa_tri   = (const float*)d_in[7];
    const float* ba_tri   = (const float*)d_in[8];
    const float* Wb_tri   = (const float*)d_in[9];
    const float* bb_tri   = (const float*)d_in[10];
    const float* Wa_fuse  = (const float*)d_in[11];
    const float* ba_fuse  = (const float*)d_in[12];
    const float* Wb_fuse  = (const float*)d_in[13];
    const float* bb_fuse  = (const float*)d_in[14];
    float* out = (float*)d_out;

    prep_kernel<<<TR_BLOCKS + W_BLOCKS, 256>>>(
        x_0, x_1,
        Wa_local, ba_local, Wb_local, bb_local,
        Wa_tri, ba_tri, Wb_tri, bb_tri,
        Wa_fuse, ba_fuse, Wb_fuse, bb_fuse);

    mesh_main_kernel<<<296, 256>>>(gemm, out);
}

// round 7
// speedup vs baseline: 1.0449x; 1.0449x over previous
#include <cuda_runtime.h>
#include <cuda_fp16.h>
#include <cstddef>

#define NB 2
#define NC 128
#define NE 60000
#define TR_BLOCKS (2 * NB * 2 * (NE / 32))          // 15000 transpose tiles
#define W_WARPS   (2 * NC * 15 + 3)
#define W_BLOCKS  ((W_WARPS + 7) / 8)
#define GROUPS2   (NB * NE / 2)                      // 60000 2-edge groups

// Transposed inputs in fp16: [tensor][b*E+e][c] (256B per edge row)
__device__ __half g_xth[2][(size_t)NB * NE * NC];
// Effective fused weights: [branch][c][s*3+k] padded to 16
__device__ float g_V[2][NC][16];
__device__ float g_cb[3];

// ---------------------------------------------------------------------------
// Kernel 1 (fused): blocks < TR_BLOCKS transpose x->fp16 (64c x 32e tiles);
// the remaining blocks fold the weights.
// ---------------------------------------------------------------------------
__global__ void __launch_bounds__(256)
prep_kernel(const float* __restrict__ x0, const float* __restrict__ x1,
    const float* __restrict__ Wa_local, const float* __restrict__ ba_local,
    const float* __restrict__ Wb_local, const float* __restrict__ bb_local,
    const float* __restrict__ Wa_tri,   const float* __restrict__ ba_tri,
    const float* __restrict__ Wb_tri,   const float* __restrict__ bb_tri,
    const float* __restrict__ Wa_fuse,  const float* __restrict__ ba_fuse,
    const float* __restrict__ Wb_fuse,  const float* __restrict__ bb_fuse)
{
    if (blockIdx.x < TR_BLOCKS) {
        __shared__ __half tile[32][66];   // [e_local][c_local], stride 66 halves
        int bx = blockIdx.x;
        const int eb = bx % (NE / 32);  bx /= (NE / 32);
        const int ch = bx & 1;          bx >>= 1;
        const int b  = bx & 1;
        const int tensor = bx >> 1;
        const float* __restrict__ src = tensor ? x1 : x0;
        const int e0 = eb * 32, c0 = ch * 64;
        const int tx = threadIdx.x & 31;
        const int ty = threadIdx.x >> 5;

#pragma unroll
        for (int i = 0; i < 8; i++) {
            int cl = ty + 8 * i;
            tile[tx][cl] = __float2half_rn(
                src[((size_t)b * NC + c0 + cl) * NE + e0 + tx]);
        }
        __syncthreads();
        __half* __restrict__ dst = g_xth[tensor];
#pragma unroll
        for (int it = 0; it < 4; it++) {
            int e = ty * 4 + it;
            unsigned v = *reinterpret_cast<const unsigned*>(&tile[e][2 * tx]);
            *reinterpret_cast<unsigned*>(
                dst + ((size_t)(b * NE + e0 + e)) * NC + c0 + 2 * tx) = v;
        }
        return;
    }

    // ---- weight folding: one warp per output ----
    const int lane = threadIdx.x & 31;
    const int w = (blockIdx.x - TR_BLOCKS) * 8 + (threadIdx.x >> 5);

    if (w < 2 * NC * 15) {
        const int t   = w / (NC * 15);
        const int rem = w - t * (NC * 15);
        const int c   = rem / 15;
        const int sk  = rem - c * 15;
        const int s   = sk / 3;
        const int k   = sk - s * 3;
        const float* Wf = t ? Wb_fuse  : Wa_fuse;
        const float* Wt = t ? Wb_tri   : Wa_tri;
        const float* Wl = t ? Wb_local : Wa_local;
        float acc = 0.f;
#pragma unroll
        for (int j = 0; j < 4; j++) {
            int o = lane + 32 * j;
            acc = fmaf(Wf[k * (2 * NC) + NC + o], Wt[(o * NC + c) * 5 + s], acc);
            if (s == 0)
                acc = fmaf(Wf[k * (2 * NC) + o], Wl[o * NC + c], acc);
        }
#pragma unroll
        for (int off = 16; off; off >>= 1)
            acc += __shfl_xor_sync(0xffffffffu, acc, off);
        if (lane == 0) {
            g_V[t][c][sk] = acc;
            if (sk == 0) g_V[t][c][15] = 0.f;
        }
    } else if (w < 2 * NC * 15 + 3) {
        const int k = w - 2 * NC * 15;
        float acc = 0.f;
#pragma unroll
        for (int j = 0; j < 4; j++) {
            int o = lane + 32 * j;
            acc = fmaf(Wa_fuse[k * 2 * NC + o],      ba_local[o], acc);
            acc = fmaf(Wa_fuse[k * 2 * NC + NC + o], ba_tri[o],   acc);
            acc = fmaf(Wb_fuse[k * 2 * NC + o],      bb_local[o], acc);
            acc = fmaf(Wb_fuse[k * 2 * NC + NC + o], bb_tri[o],   acc);
        }
#pragma unroll
        for (int off = 16; off; off >>= 1)
            acc += __shfl_xor_sync(0xffffffffu, acc, off);
        if (lane == 0)
            g_cb[k] = acc + ba_fuse[k] + bb_fuse[k];
    }
}

// ---------------------------------------------------------------------------
// Kernel 2: main gather + fused dot. One warp per 2 edges, both tensors;
// lane owns channels 4*lane..4*lane+3; half2 weights (60 regs), HFMA2 dot.
// Software-pipelined: next iteration's neighbor indices are prefetched
// before the current edges' compute, breaking the gi->rows serial chain.
// ---------------------------------------------------------------------------
__device__ __forceinline__ __half2 u2h(const unsigned& u)
{
    return *reinterpret_cast<const __half2*>(&u);
}

// one tensor's contribution for one edge from 5 gathered rows
__device__ __forceinline__ void dot_tensor(
    const uint2 r0, const uint2 r1, const uint2 r2,
    const uint2 r3, const uint2 r4,
    const __half2 Va[15], const __half2 Vb[15],
    __half2& h0, __half2& h1, __half2& h2)
{
    __half2 n1a = u2h(r1.x), n1b = u2h(r1.y);
    __half2 n2a = u2h(r2.x), n2b = u2h(r2.y);
    __half2 n3a = u2h(r3.x), n3b = u2h(r3.y);
    __half2 n4a = u2h(r4.x), n4b = u2h(r4.y);

    __half2 Ga[5], Gb[5];
    Ga[0] = u2h(r0.x);
    Gb[0] = u2h(r0.y);
    Ga[1] = __hadd2(n1a, n3a);  Gb[1] = __hadd2(n1b, n3b);
    Ga[2] = __hadd2(n2a, n4a);  Gb[2] = __hadd2(n2b, n4b);
    Ga[3] = __habs2(__hsub2(n1a, n3a));  Gb[3] = __habs2(__hsub2(n1b, n3b));
    Ga[4] = __habs2(__hsub2(n2a, n4a));  Gb[4] = __habs2(__hsub2(n2b, n4b));

    __half2 aa0 = __hmul2(Va[0], Ga[0]);
    __half2 aa1 = __hmul2(Va[1], Ga[0]);
    __half2 aa2 = __hmul2(Va[2], Ga[0]);
    __half2 ab0 = __hmul2(Vb[0], Gb[0]);
    __half2 ab1 = __hmul2(Vb[1], Gb[0]);
    __half2 ab2 = __hmul2(Vb[2], Gb[0]);
#pragma unroll
    for (int s = 1; s < 5; s++) {
        aa0 = __hfma2(Va[s * 3 + 0], Ga[s], aa0);
        aa1 = __hfma2(Va[s * 3 + 1], Ga[s], aa1);
        aa2 = __hfma2(Va[s * 3 + 2], Ga[s], aa2);
        ab0 = __hfma2(Vb[s * 3 + 0], Gb[s], ab0);
        ab1 = __hfma2(Vb[s * 3 + 1], Gb[s], ab1);
        ab2 = __hfma2(Vb[s * 3 + 2], Gb[s], ab2);
    }
    h0 = __hadd2(h0, __hadd2(aa0, ab0));
    h1 = __hadd2(h1, __hadd2(aa1, ab1));
    h2 = __hadd2(h2, __hadd2(aa2, ab2));
}

__global__ void __launch_bounds__(256, 2)
mesh_main_kernel(const int* __restrict__ gemm, float* __restrict__ out)
{
    const int lane = threadIdx.x & 31;
    const int gw   = blockIdx.x * 8 + (threadIdx.x >> 5);
    const int W    = gridDim.x * 8;

    // weights as half2: [tensor*2 + slot][15]  (60 regs)
    __half2 Vp[4][15];
#pragma unroll
    for (int t = 0; t < 2; t++)
#pragma unroll
        for (int j = 0; j < 2; j++) {
            const float* r0 = g_V[t][4 * lane + 2 * j];
            const float* r1 = g_V[t][4 * lane + 2 * j + 1];
#pragma unroll
            for (int sk = 0; sk < 15; sk++)
                Vp[t * 2 + j][sk] = __floats2half2_rn(r0[sk], r1[sk]);
        }
    float cbk = (lane < 6) ? g_cb[lane % 3] : 0.f;

    const int4* __restrict__ gi4 = reinterpret_cast<const int4*>(gemm);

    int g = gw;
    if (g >= GROUPS2) return;

    // prologue: prefetch first iteration's indices
    int e0 = 2 * g;
    int b  = (e0 >= NE) ? 1 : 0;
    int eb = e0 - b * NE;
    int4 ga = gi4[(size_t)b * NE + eb];
    int4 gb = gi4[(size_t)b * NE + eb + 1];

    while (g < GROUPS2) {
        // ---- prefetch NEXT iteration's indices (clamped) ----
        const int gn  = g + W;
        const int gnc = (gn < GROUPS2) ? gn : gw;
        const int e0n = 2 * gnc;
        const int bn  = (e0n >= NE) ? 1 : 0;
        const int ebn = e0n - bn * NE;
        const int4 ga_n = gi4[(size_t)bn * NE + ebn];
        const int4 gb_n = gi4[(size_t)bn * NE + ebn + 1];

        const __half* __restrict__ b0 = g_xth[0] + (size_t)b * NE * NC + lane * 4;
        const __half* __restrict__ b1 = g_xth[1] + (size_t)b * NE * NC + lane * 4;

        float res[6];

        // ---- edge A: batch 10 row loads, then compute ----
        {
            uint2 ra0 = *reinterpret_cast<const uint2*>(b0 + (size_t)eb   * NC);
            uint2 ra1 = *reinterpret_cast<const uint2*>(b0 + (size_t)ga.x * NC);
            uint2 ra2 = *reinterpret_cast<const uint2*>(b0 + (size_t)ga.y * NC);
            uint2 ra3 = *reinterpret_cast<const uint2*>(b0 + (size_t)ga.z * NC);
            uint2 ra4 = *reinterpret_cast<const uint2*>(b0 + (size_t)ga.w * NC);
            uint2 rb0 = *reinterpret_cast<const uint2*>(b1 + (size_t)eb   * NC);
            uint2 rb1 = *reinterpret_cast<const uint2*>(b1 + (size_t)ga.x * NC);
            uint2 rb2 = *reinterpret_cast<const uint2*>(b1 + (size_t)ga.y * NC);
            uint2 rb3 = *reinterpret_cast<const uint2*>(b1 + (size_t)ga.z * NC);
            uint2 rb4 = *reinterpret_cast<const uint2*>(b1 + (size_t)ga.w * NC);

            __half2 h0 = __float2half2_rn(0.f), h1 = h0, h2 = h0;
            dot_tensor(ra0, ra1, ra2, ra3, ra4, Vp[0], Vp[1], h0, h1, h2);
            dot_tensor(rb0, rb1, rb2, rb3, rb4, Vp[2], Vp[3], h0, h1, h2);
            float2 f0 = __half22float2(h0);
            float2 f1 = __half22float2(h1);
            float2 f2 = __half22float2(h2);
            res[0] = f0.x + f0.y;
            res[1] = f1.x + f1.y;
            res[2] = f2.x + f2.y;
        }

        // ---- edge B: batch 10 row loads, then compute ----
        {
            const int e = eb + 1;
            uint2 ra0 = *reinterpret_cast<const uint2*>(b0 + (size_t)e    * NC);
            uint2 ra1 = *reinterpret_cast<const uint2*>(b0 + (size_t)gb.x * NC);
            uint2 ra2 = *reinterpret_cast<const uint2*>(b0 + (size_t)gb.y * NC);
            uint2 ra3 = *reinterpret_cast<const uint2*>(b0 + (size_t)gb.z * NC);
            uint2 ra4 = *reinterpret_cast<const uint2*>(b0 + (size_t)gb.w * NC);
            uint2 rb0 = *reinterpret_cast<const uint2*>(b1 + (size_t)e    * NC);
            uint2 rb1 = *reinterpret_cast<const uint2*>(b1 + (size_t)gb.x * NC);
            uint2 rb2 = *reinterpret_cast<const uint2*>(b1 + (size_t)gb.y * NC);
            uint2 rb3 = *reinterpret_cast<const uint2*>(b1 + (size_t)gb.z * NC);
            uint2 rb4 = *reinterpret_cast<const uint2*>(b1 + (size_t)gb.w * NC);

            __half2 h0 = __float2half2_rn(0.f), h1 = h0, h2 = h0;
            dot_tensor(ra0, ra1, ra2, ra3, ra4, Vp[0], Vp[1], h0, h1, h2);
            dot_tensor(rb0, rb1, rb2, rb3, rb4, Vp[2], Vp[3], h0, h1, h2);
            float2 f0 = __half22float2(h0);
            float2 f1 = __half22float2(h1);
            float2 f2 = __half22float2(h2);
            res[3] = f0.x + f0.y;
            res[4] = f1.x + f1.y;
            res[5] = f2.x + f2.y;
        }

#pragma unroll
        for (int off = 16; off; off >>= 1)
#pragma unroll
            for (int r = 0; r < 6; r++)
                res[r] += __shfl_xor_sync(0xffffffffu, res[r], off);

        if (lane < 6) {
            const int u = lane / 3, k = lane - 3 * u;
            out[((size_t)b * 3 + k) * NE + eb + u] = res[lane] + cbk;
        }

        // rotate pipeline
        g  = gn;
        b  = bn;
        eb = ebn;
        ga = ga_n;
        gb = gb_n;
    }
}

// ---------------------------------------------------------------------------
extern "C" void kernel_launch(void* const* d_in, const int* in_sizes, int n_in,
                              void* d_out, int out_size)
{
    const float* x_0      = (const float*)d_in[0];
    const float* x_1      = (const float*)d_in[1];
    const int*   gemm     = (const int*)  d_in[2];
    const float* Wa_local = (const float*)d_in[3];
    const float* ba_local = (const float*)d_in[4];
    const float* Wb_local = (const float*)d_in[5];
    const float* bb_local = (const float*)d_in[6];
    const float* Wa_tri   = (const float*)d_in[7];
    const float* ba_tri   = (const float*)d_in[8];
    const float* Wb_tri   = (const float*)d_in[9];
    const float* bb_tri   = (const float*)d_in[10];
    const float* Wa_fuse  = (const float*)d_in[11];
    const float* ba_fuse  = (const float*)d_in[12];
    const float* Wb_fuse  = (const float*)d_in[13];
    const float* bb_fuse  = (const float*)d_in[14];
    float* out = (float*)d_out;

    prep_kernel<<<TR_BLOCKS + W_BLOCKS, 256>>>(
        x_0, x_1,
        Wa_local, ba_local, Wb_local, bb_local,
        Wa_tri, ba_tri, Wb_tri, bb_tri,
        Wa_fuse, ba_fuse, Wb_fuse, bb_fuse);

    mesh_main_kernel<<<296, 256>>>(gemm, out);
}

// round 8
// speedup vs baseline: 1.0622x; 1.0165x over previous
#include <cuda_runtime.h>
#include <cuda_fp16.h>
#include <cstddef>

#define NB 2
#define NC 128
#define NE 60000
#define TR_BLOCKS (2 * NB * 2 * (NE / 32))          // 15000 transpose tiles
#define W_WARPS   (2 * NC * 15 + 3)
#define W_BLOCKS  ((W_WARPS + 7) / 8)
#define GROUPS4   (NB * NE / 4)                      // 30000 4-edge groups

// Transposed inputs in fp16: [tensor][b*E+e][c] (256B per edge row)
__device__ __half g_xth[2][(size_t)NB * NE * NC];
// Effective fused weights: [branch][c][s*3+k] padded to 16
__device__ float g_V[2][NC][16];
__device__ float g_cb[3];

// ---------------------------------------------------------------------------
// Kernel 1 (fused): blocks < TR_BLOCKS transpose x->fp16 (64c x 32e tiles);
// the remaining blocks fold the weights.
// ---------------------------------------------------------------------------
__global__ void __launch_bounds__(256)
prep_kernel(const float* __restrict__ x0, const float* __restrict__ x1,
    const float* __restrict__ Wa_local, const float* __restrict__ ba_local,
    const float* __restrict__ Wb_local, const float* __restrict__ bb_local,
    const float* __restrict__ Wa_tri,   const float* __restrict__ ba_tri,
    const float* __restrict__ Wb_tri,   const float* __restrict__ bb_tri,
    const float* __restrict__ Wa_fuse,  const float* __restrict__ ba_fuse,
    const float* __restrict__ Wb_fuse,  const float* __restrict__ bb_fuse)
{
    if (blockIdx.x < TR_BLOCKS) {
        __shared__ __half tile[32][66];   // [e_local][c_local], stride 66 halves
        int bx = blockIdx.x;
        const int eb = bx % (NE / 32);  bx /= (NE / 32);
        const int ch = bx & 1;          bx >>= 1;
        const int b  = bx & 1;
        const int tensor = bx >> 1;
        const float* __restrict__ src = tensor ? x1 : x0;
        const int e0 = eb * 32, c0 = ch * 64;
        const int tx = threadIdx.x & 31;
        const int ty = threadIdx.x >> 5;

#pragma unroll
        for (int i = 0; i < 8; i++) {
            int cl = ty + 8 * i;
            tile[tx][cl] = __float2half_rn(
                src[((size_t)b * NC + c0 + cl) * NE + e0 + tx]);
        }
        __syncthreads();
        __half* __restrict__ dst = g_xth[tensor];
#pragma unroll
        for (int it = 0; it < 4; it++) {
            int e = ty * 4 + it;
            unsigned v = *reinterpret_cast<const unsigned*>(&tile[e][2 * tx]);
            *reinterpret_cast<unsigned*>(
                dst + ((size_t)(b * NE + e0 + e)) * NC + c0 + 2 * tx) = v;
        }
        return;
    }

    // ---- weight folding: one warp per output ----
    const int lane = threadIdx.x & 31;
    const int w = (blockIdx.x - TR_BLOCKS) * 8 + (threadIdx.x >> 5);

    if (w < 2 * NC * 15) {
        const int t   = w / (NC * 15);
        const int rem = w - t * (NC * 15);
        const int c   = rem / 15;
        const int sk  = rem - c * 15;
        const int s   = sk / 3;
        const int k   = sk - s * 3;
        const float* Wf = t ? Wb_fuse  : Wa_fuse;
        const float* Wt = t ? Wb_tri   : Wa_tri;
        const float* Wl = t ? Wb_local : Wa_local;
        float acc = 0.f;
#pragma unroll
        for (int j = 0; j < 4; j++) {
            int o = lane + 32 * j;
            acc = fmaf(Wf[k * (2 * NC) + NC + o], Wt[(o * NC + c) * 5 + s], acc);
            if (s == 0)
                acc = fmaf(Wf[k * (2 * NC) + o], Wl[o * NC + c], acc);
        }
#pragma unroll
        for (int off = 16; off; off >>= 1)
            acc += __shfl_xor_sync(0xffffffffu, acc, off);
        if (lane == 0) {
            g_V[t][c][sk] = acc;
            if (sk == 0) g_V[t][c][15] = 0.f;
        }
    } else if (w < 2 * NC * 15 + 3) {
        const int k = w - 2 * NC * 15;
        float acc = 0.f;
#pragma unroll
        for (int j = 0; j < 4; j++) {
            int o = lane + 32 * j;
            acc = fmaf(Wa_fuse[k * 2 * NC + o],      ba_local[o], acc);
            acc = fmaf(Wa_fuse[k * 2 * NC + NC + o], ba_tri[o],   acc);
            acc = fmaf(Wb_fuse[k * 2 * NC + o],      bb_local[o], acc);
            acc = fmaf(Wb_fuse[k * 2 * NC + NC + o], bb_tri[o],   acc);
        }
#pragma unroll
        for (int off = 16; off; off >>= 1)
            acc += __shfl_xor_sync(0xffffffffu, acc, off);
        if (lane == 0)
            g_cb[k] = acc + ba_fuse[k] + bb_fuse[k];
    }
}

// ---------------------------------------------------------------------------
// Kernel 2: main gather + fused dot. One warp per 4 edges (both tensors);
// lane owns channels 4*lane..4*lane+3; half2 weights (60 regs), HFMA2 dot.
// Two batched load waves of 20, ONE deferred 12-value butterfly per 4 edges.
// ---------------------------------------------------------------------------
__device__ __forceinline__ __half2 u2h(const unsigned& u)
{
    return *reinterpret_cast<const __half2*>(&u);
}

// one tensor's contribution for one edge from 5 gathered rows
__device__ __forceinline__ void dot_tensor(
    const uint2 r0, const uint2 r1, const uint2 r2,
    const uint2 r3, const uint2 r4,
    const __half2 Va[15], const __half2 Vb[15],
    __half2& h0, __half2& h1, __half2& h2)
{
    __half2 n1a = u2h(r1.x), n1b = u2h(r1.y);
    __half2 n2a = u2h(r2.x), n2b = u2h(r2.y);
    __half2 n3a = u2h(r3.x), n3b = u2h(r3.y);
    __half2 n4a = u2h(r4.x), n4b = u2h(r4.y);

    __half2 Ga[5], Gb[5];
    Ga[0] = u2h(r0.x);
    Gb[0] = u2h(r0.y);
    Ga[1] = __hadd2(n1a, n3a);  Gb[1] = __hadd2(n1b, n3b);
    Ga[2] = __hadd2(n2a, n4a);  Gb[2] = __hadd2(n2b, n4b);
    Ga[3] = __habs2(__hsub2(n1a, n3a));  Gb[3] = __habs2(__hsub2(n1b, n3b));
    Ga[4] = __habs2(__hsub2(n2a, n4a));  Gb[4] = __habs2(__hsub2(n2b, n4b));

    __half2 aa0 = __hmul2(Va[0], Ga[0]);
    __half2 aa1 = __hmul2(Va[1], Ga[0]);
    __half2 aa2 = __hmul2(Va[2], Ga[0]);
    __half2 ab0 = __hmul2(Vb[0], Gb[0]);
    __half2 ab1 = __hmul2(Vb[1], Gb[0]);
    __half2 ab2 = __hmul2(Vb[2], Gb[0]);
#pragma unroll
    for (int s = 1; s < 5; s++) {
        aa0 = __hfma2(Va[s * 3 + 0], Ga[s], aa0);
        aa1 = __hfma2(Va[s * 3 + 1], Ga[s], aa1);
        aa2 = __hfma2(Va[s * 3 + 2], Ga[s], aa2);
        ab0 = __hfma2(Vb[s * 3 + 0], Gb[s], ab0);
        ab1 = __hfma2(Vb[s * 3 + 1], Gb[s], ab1);
        ab2 = __hfma2(Vb[s * 3 + 2], Gb[s], ab2);
    }
    h0 = __hadd2(h0, __hadd2(aa0, ab0));
    h1 = __hadd2(h1, __hadd2(aa1, ab1));
    h2 = __hadd2(h2, __hadd2(aa2, ab2));
}

// one PAIR of edges: 20 batched loads, then two computes -> res[0..5]
__device__ __forceinline__ void do_pair(
    const __half* __restrict__ b0, const __half* __restrict__ b1,
    int e, const int4 gi0, const int4 gi1,
    const __half2 Vp[4][15], float* __restrict__ res)
{
    // edge e rows (both tensors)
    uint2 a0 = *reinterpret_cast<const uint2*>(b0 + (size_t)e     * NC);
    uint2 a1 = *reinterpret_cast<const uint2*>(b0 + (size_t)gi0.x * NC);
    uint2 a2 = *reinterpret_cast<const uint2*>(b0 + (size_t)gi0.y * NC);
    uint2 a3 = *reinterpret_cast<const uint2*>(b0 + (size_t)gi0.z * NC);
    uint2 a4 = *reinterpret_cast<const uint2*>(b0 + (size_t)gi0.w * NC);
    uint2 a5 = *reinterpret_cast<const uint2*>(b1 + (size_t)e     * NC);
    uint2 a6 = *reinterpret_cast<const uint2*>(b1 + (size_t)gi0.x * NC);
    uint2 a7 = *reinterpret_cast<const uint2*>(b1 + (size_t)gi0.y * NC);
    uint2 a8 = *reinterpret_cast<const uint2*>(b1 + (size_t)gi0.z * NC);
    uint2 a9 = *reinterpret_cast<const uint2*>(b1 + (size_t)gi0.w * NC);
    // edge e+1 rows
    uint2 c0 = *reinterpret_cast<const uint2*>(b0 + (size_t)(e+1) * NC);
    uint2 c1 = *reinterpret_cast<const uint2*>(b0 + (size_t)gi1.x * NC);
    uint2 c2 = *reinterpret_cast<const uint2*>(b0 + (size_t)gi1.y * NC);
    uint2 c3 = *reinterpret_cast<const uint2*>(b0 + (size_t)gi1.z * NC);
    uint2 c4 = *reinterpret_cast<const uint2*>(b0 + (size_t)gi1.w * NC);
    uint2 c5 = *reinterpret_cast<const uint2*>(b1 + (size_t)(e+1) * NC);
    uint2 c6 = *reinterpret_cast<const uint2*>(b1 + (size_t)gi1.x * NC);
    uint2 c7 = *reinterpret_cast<const uint2*>(b1 + (size_t)gi1.y * NC);
    uint2 c8 = *reinterpret_cast<const uint2*>(b1 + (size_t)gi1.z * NC);
    uint2 c9 = *reinterpret_cast<const uint2*>(b1 + (size_t)gi1.w * NC);

    {
        __half2 h0 = __float2half2_rn(0.f), h1 = h0, h2 = h0;
        dot_tensor(a0, a1, a2, a3, a4, Vp[0], Vp[1], h0, h1, h2);
        dot_tensor(a5, a6, a7, a8, a9, Vp[2], Vp[3], h0, h1, h2);
        float2 f0 = __half22float2(h0);
        float2 f1 = __half22float2(h1);
        float2 f2 = __half22float2(h2);
        res[0] = f0.x + f0.y;
        res[1] = f1.x + f1.y;
        res[2] = f2.x + f2.y;
    }
    {
        __half2 h0 = __float2half2_rn(0.f), h1 = h0, h2 = h0;
        dot_tensor(c0, c1, c2, c3, c4, Vp[0], Vp[1], h0, h1, h2);
        dot_tensor(c5, c6, c7, c8, c9, Vp[2], Vp[3], h0, h1, h2);
        float2 f0 = __half22float2(h0);
        float2 f1 = __half22float2(h1);
        float2 f2 = __half22float2(h2);
        res[3] = f0.x + f0.y;
        res[4] = f1.x + f1.y;
        res[5] = f2.x + f2.y;
    }
}

__global__ void __launch_bounds__(256, 2)
mesh_main_kernel(const int* __restrict__ gemm, float* __restrict__ out)
{
    const int lane = threadIdx.x & 31;
    const int gw   = blockIdx.x * 8 + (threadIdx.x >> 5);
    const int W    = gridDim.x * 8;

    // weights as half2: [tensor*2 + slot][15]  (60 regs)
    __half2 Vp[4][15];
#pragma unroll
    for (int t = 0; t < 2; t++)
#pragma unroll
        for (int j = 0; j < 2; j++) {
            const float* r0 = g_V[t][4 * lane + 2 * j];
            const float* r1 = g_V[t][4 * lane + 2 * j + 1];
#pragma unroll
            for (int sk = 0; sk < 15; sk++)
                Vp[t * 2 + j][sk] = __floats2half2_rn(r0[sk], r1[sk]);
        }
    float cbk = (lane < 12) ? g_cb[lane % 3] : 0.f;

    const int4* __restrict__ gi4 = reinterpret_cast<const int4*>(gemm);

    int g = gw;
    if (g >= GROUPS4) return;

    // prologue: first group's pair-0 indices
    int e0 = 4 * g;
    int b  = (e0 >= NE) ? 1 : 0;
    int eb = e0 - b * NE;
    int4 gA = gi4[(size_t)b * NE + eb];
    int4 gB = gi4[(size_t)b * NE + eb + 1];

    while (g < GROUPS4) {
        // current group's pair-1 indices
        const int4 gC = gi4[(size_t)b * NE + eb + 2];
        const int4 gD = gi4[(size_t)b * NE + eb + 3];

        // next group's pair-0 indices (clamped)
        const int gn  = g + W;
        const int gnc = (gn < GROUPS4) ? gn : gw;
        const int e0n = 4 * gnc;
        const int bn  = (e0n >= NE) ? 1 : 0;
        const int ebn = e0n - bn * NE;
        const int4 gA_n = gi4[(size_t)bn * NE + ebn];
        const int4 gB_n = gi4[(size_t)bn * NE + ebn + 1];

        const __half* __restrict__ b0 = g_xth[0] + (size_t)b * NE * NC + lane * 4;
        const __half* __restrict__ b1 = g_xth[1] + (size_t)b * NE * NC + lane * 4;

        float res[12];
        do_pair(b0, b1, eb,     gA, gB, Vp, res);
        do_pair(b0, b1, eb + 2, gC, gD, Vp, res + 6);

        // single deferred butterfly: 12 parallel chains x 5 rounds
#pragma unroll
        for (int off = 16; off; off >>= 1)
#pragma unroll
            for (int r = 0; r < 12; r++)
                res[r] += __shfl_xor_sync(0xffffffffu, res[r], off);

        if (lane < 12) {
            const int u = lane >> 2 == 0 ? lane / 3 : lane / 3; // u = lane/3
            const int k = lane - 3 * (lane / 3);
            out[((size_t)b * 3 + k) * NE + eb + (lane / 3)] = res[lane] + cbk;
        }

        // rotate pipeline
        g  = gn;
        b  = bn;
        eb = ebn;
        gA = gA_n;
        gB = gB_n;
    }
}

// ---------------------------------------------------------------------------
extern "C" void kernel_launch(void* const* d_in, const int* in_sizes, int n_in,
                              void* d_out, int out_size)
{
    const float* x_0      = (const float*)d_in[0];
    const float* x_1      = (const float*)d_in[1];
    const int*   gemm     = (const int*)  d_in[2];
    const float* Wa_local = (const float*)d_in[3];
    const float* ba_local = (const float*)d_in[4];
    const float* Wb_local = (const float*)d_in[5];
    const float* bb_local = (const float*)d_in[6];
    const float* Wa_tri   = (const float*)d_in[7];
    const float* ba_tri   = (const float*)d_in[8];
    const float* Wb_tri   = (const float*)d_in[9];
    const float* bb_tri   = (const float*)d_in[10];
    const float* Wa_fuse  = (const float*)d_in[11];
    const float* ba_fuse  = (const float*)d_in[12];
    const float* Wb_fuse  = (const float*)d_in[13];
    const float* bb_fuse  = (const float*)d_in[14];
    float* out = (float*)d_out;

    prep_kernel<<<TR_BLOCKS + W_BLOCKS, 256>>>(
        x_0, x_1,
        Wa_local, ba_local, Wb_local, bb_local,
        Wa_tri, ba_tri, Wb_tri, bb_tri,
        Wa_fuse, ba_fuse, Wb_fuse, bb_fuse);

    mesh_main_kernel<<<296, 256>>>(gemm, out);
}

// round 9
// speedup vs baseline: 1.0667x; 1.0042x over previous
#include <cuda_runtime.h>
#include <cuda_fp16.h>
#include <cstddef>

#define NB 2
#define NC 128
#define TWOC 256
#define NE 60000
#define TR_BLOCKS (2 * NB * 2 * (NE / 32))          // 15000 transpose tiles
#define W_WARPS   (2 * NC * 15 + 3)
#define W_BLOCKS  ((W_WARPS + 7) / 8)
#define GROUPS4   (NB * NE / 4)                      // 30000 4-edge groups

// Transposed inputs in fp16, tensor-interleaved: [b][e][tensor][c]
// One edge row = 2*128 halves = 512B -> a single warp LDG.128 covers it.
__device__ __half g_xti[(size_t)NB * NE * TWOC];
// Effective fused weights: [branch][c][s*3+k] padded to 16
__device__ float g_V[2][NC][16];
__device__ float g_cb[3];

// ---------------------------------------------------------------------------
// Kernel 1 (fused): blocks < TR_BLOCKS transpose x->fp16 (64c x 32e tiles)
// into the interleaved layout; the remaining blocks fold the weights.
// ---------------------------------------------------------------------------
__global__ void __launch_bounds__(256)
prep_kernel(const float* __restrict__ x0, const float* __restrict__ x1,
    const float* __restrict__ Wa_local, const float* __restrict__ ba_local,
    const float* __restrict__ Wb_local, const float* __restrict__ bb_local,
    const float* __restrict__ Wa_tri,   const float* __restrict__ ba_tri,
    const float* __restrict__ Wb_tri,   const float* __restrict__ bb_tri,
    const float* __restrict__ Wa_fuse,  const float* __restrict__ ba_fuse,
    const float* __restrict__ Wb_fuse,  const float* __restrict__ bb_fuse)
{
    if (blockIdx.x < TR_BLOCKS) {
        __shared__ __half tile[32][66];   // [e_local][c_local], stride 66 halves
        int bx = blockIdx.x;
        const int eb = bx % (NE / 32);  bx /= (NE / 32);
        const int ch = bx & 1;          bx >>= 1;
        const int b  = bx & 1;
        const int tensor = bx >> 1;
        const float* __restrict__ src = tensor ? x1 : x0;
        const int e0 = eb * 32, c0 = ch * 64;
        const int tx = threadIdx.x & 31;
        const int ty = threadIdx.x >> 5;

#pragma unroll
        for (int i = 0; i < 8; i++) {
            int cl = ty + 8 * i;
            tile[tx][cl] = __float2half_rn(
                src[((size_t)b * NC + c0 + cl) * NE + e0 + tx]);
        }
        __syncthreads();
#pragma unroll
        for (int it = 0; it < 4; it++) {
            int e = ty * 4 + it;
            unsigned v = *reinterpret_cast<const unsigned*>(&tile[e][2 * tx]);
            *reinterpret_cast<unsigned*>(
                g_xti + ((size_t)(b * NE + e0 + e)) * TWOC
                      + tensor * NC + c0 + 2 * tx) = v;
        }
        return;
    }

    // ---- weight folding: one warp per output ----
    const int lane = threadIdx.x & 31;
    const int w = (blockIdx.x - TR_BLOCKS) * 8 + (threadIdx.x >> 5);

    if (w < 2 * NC * 15) {
        const int t   = w / (NC * 15);
        const int rem = w - t * (NC * 15);
        const int c   = rem / 15;
        const int sk  = rem - c * 15;
        const int s   = sk / 3;
        const int k   = sk - s * 3;
        const float* Wf = t ? Wb_fuse  : Wa_fuse;
        const float* Wt = t ? Wb_tri   : Wa_tri;
        const float* Wl = t ? Wb_local : Wa_local;
        float acc = 0.f;
#pragma unroll
        for (int j = 0; j < 4; j++) {
            int o = lane + 32 * j;
            acc = fmaf(Wf[k * (2 * NC) + NC + o], Wt[(o * NC + c) * 5 + s], acc);
            if (s == 0)
                acc = fmaf(Wf[k * (2 * NC) + o], Wl[o * NC + c], acc);
        }
#pragma unroll
        for (int off = 16; off; off >>= 1)
            acc += __shfl_xor_sync(0xffffffffu, acc, off);
        if (lane == 0) {
            g_V[t][c][sk] = acc;
            if (sk == 0) g_V[t][c][15] = 0.f;
        }
    } else if (w < 2 * NC * 15 + 3) {
        const int k = w - 2 * NC * 15;
        float acc = 0.f;
#pragma unroll
        for (int j = 0; j < 4; j++) {
            int o = lane + 32 * j;
            acc = fmaf(Wa_fuse[k * 2 * NC + o],      ba_local[o], acc);
            acc = fmaf(Wa_fuse[k * 2 * NC + NC + o], ba_tri[o],   acc);
            acc = fmaf(Wb_fuse[k * 2 * NC + o],      bb_local[o], acc);
            acc = fmaf(Wb_fuse[k * 2 * NC + NC + o], bb_tri[o],   acc);
        }
#pragma unroll
        for (int off = 16; off; off >>= 1)
            acc += __shfl_xor_sync(0xffffffffu, acc, off);
        if (lane == 0)
            g_cb[k] = acc + ba_fuse[k] + bb_fuse[k];
    }
}

// ---------------------------------------------------------------------------
// Kernel 2: main gather + fused dot over the interleaved layout.
// One warp per 4 edges; one LDG.128 fetches a whole 512B combined row
// (lane 0-15 -> tensor0 channels 8L.., lane 16-31 -> tensor1). 5 LDG/edge.
// HFMA2 dot with per-lane 60 half2 weights; deferred 12-value butterfly.
// ---------------------------------------------------------------------------
__device__ __forceinline__ __half2 u2h(const unsigned& u)
{
    return *reinterpret_cast<const __half2*>(&u);
}

// one edge from 5 gathered 512B rows -> res[0..2]
__device__ __forceinline__ void edge_dot(
    const uint4 r0, const uint4 r1, const uint4 r2,
    const uint4 r3, const uint4 r4,
    const __half2 Vp[4][15], float* __restrict__ res)
{
    const __half2 z = __float2half2_rn(0.f);
    __half2 A0 = z, A1 = z, A2 = z, B0 = z, B1 = z, B2 = z;

#define DO_SLOT(j, X0, X1, X2, X3, X4, P0, P1, P2)                        \
    {                                                                     \
        __half2 G0 = u2h(X0);                                             \
        __half2 n1 = u2h(X1), n2 = u2h(X2), n3 = u2h(X3), n4 = u2h(X4);   \
        __half2 G1 = __hadd2(n1, n3), G2 = __hadd2(n2, n4);               \
        __half2 G3 = __habs2(__hsub2(n1, n3));                            \
        __half2 G4 = __habs2(__hsub2(n2, n4));                            \
        P0 = __hfma2(Vp[j][0],  G0, P0);                                  \
        P1 = __hfma2(Vp[j][1],  G0, P1);                                  \
        P2 = __hfma2(Vp[j][2],  G0, P2);                                  \
        P0 = __hfma2(Vp[j][3],  G1, P0);                                  \
        P1 = __hfma2(Vp[j][4],  G1, P1);                                  \
        P2 = __hfma2(Vp[j][5],  G1, P2);                                  \
        P0 = __hfma2(Vp[j][6],  G2, P0);                                  \
        P1 = __hfma2(Vp[j][7],  G2, P1);                                  \
        P2 = __hfma2(Vp[j][8],  G2, P2);                                  \
        P0 = __hfma2(Vp[j][9],  G3, P0);                                  \
        P1 = __hfma2(Vp[j][10], G3, P1);                                  \
        P2 = __hfma2(Vp[j][11], G3, P2);                                  \
        P0 = __hfma2(Vp[j][12], G4, P0);                                  \
        P1 = __hfma2(Vp[j][13], G4, P1);                                  \
        P2 = __hfma2(Vp[j][14], G4, P2);                                  \
    }

    DO_SLOT(0, r0.x, r1.x, r2.x, r3.x, r4.x, A0, A1, A2)
    DO_SLOT(1, r0.y, r1.y, r2.y, r3.y, r4.y, A0, A1, A2)
    DO_SLOT(2, r0.z, r1.z, r2.z, r3.z, r4.z, B0, B1, B2)
    DO_SLOT(3, r0.w, r1.w, r2.w, r3.w, r4.w, B0, B1, B2)
#undef DO_SLOT

    float2 a0 = __half22float2(A0), b0 = __half22float2(B0);
    float2 a1 = __half22float2(A1), b1 = __half22float2(B1);
    float2 a2 = __half22float2(A2), b2 = __half22float2(B2);
    res[0] = (a0.x + a0.y) + (b0.x + b0.y);
    res[1] = (a1.x + a1.y) + (b1.x + b1.y);
    res[2] = (a2.x + a2.y) + (b2.x + b2.y);
}

// one PAIR of edges: 10 batched LDG.128, then two computes -> res[0..5]
__device__ __forceinline__ void do_pair(
    const __half* __restrict__ base,
    int e, const int4 gi0, const int4 gi1,
    const __half2 Vp[4][15], float* __restrict__ res)
{
    uint4 a0 = *reinterpret_cast<const uint4*>(base + (size_t)e     * TWOC);
    uint4 a1 = *reinterpret_cast<const uint4*>(base + (size_t)gi0.x * TWOC);
    uint4 a2 = *reinterpret_cast<const uint4*>(base + (size_t)gi0.y * TWOC);
    uint4 a3 = *reinterpret_cast<const uint4*>(base + (size_t)gi0.z * TWOC);
    uint4 a4 = *reinterpret_cast<const uint4*>(base + (size_t)gi0.w * TWOC);
    uint4 c0 = *reinterpret_cast<const uint4*>(base + (size_t)(e+1) * TWOC);
    uint4 c1 = *reinterpret_cast<const uint4*>(base + (size_t)gi1.x * TWOC);
    uint4 c2 = *reinterpret_cast<const uint4*>(base + (size_t)gi1.y * TWOC);
    uint4 c3 = *reinterpret_cast<const uint4*>(base + (size_t)gi1.z * TWOC);
    uint4 c4 = *reinterpret_cast<const uint4*>(base + (size_t)gi1.w * TWOC);

    edge_dot(a0, a1, a2, a3, a4, Vp, res);
    edge_dot(c0, c1, c2, c3, c4, Vp, res + 3);
}

__global__ void __launch_bounds__(256, 2)
mesh_main_kernel(const int* __restrict__ gemm, float* __restrict__ out)
{
    const int lane = threadIdx.x & 31;
    const int gw   = blockIdx.x * 8 + (threadIdx.x >> 5);
    const int W    = gridDim.x * 8;

    // lane's tensor + channel base within the combined 256-half row
    const int lt = lane >> 4;              // tensor
    const int lc = (lane & 15) * 8;        // channel base (8 channels)

    // weights as half2: [slot j][sk], slot j covers channels lc+2j, lc+2j+1
    __half2 Vp[4][15];
#pragma unroll
    for (int j = 0; j < 4; j++) {
        const float* r0 = g_V[lt][lc + 2 * j];
        const float* r1 = g_V[lt][lc + 2 * j + 1];
#pragma unroll
        for (int sk = 0; sk < 15; sk++)
            Vp[j][sk] = __floats2half2_rn(r0[sk], r1[sk]);
    }
    float cbk = (lane < 12) ? g_cb[lane % 3] : 0.f;

    const int4* __restrict__ gi4 = reinterpret_cast<const int4*>(gemm);

    int g = gw;
    if (g >= GROUPS4) return;

    // prologue: first group's pair-0 indices
    int e0 = 4 * g;
    int b  = (e0 >= NE) ? 1 : 0;
    int eb = e0 - b * NE;
    int4 gA = gi4[(size_t)b * NE + eb];
    int4 gB = gi4[(size_t)b * NE + eb + 1];

    while (g < GROUPS4) {
        const int4 gC = gi4[(size_t)b * NE + eb + 2];
        const int4 gD = gi4[(size_t)b * NE + eb + 3];

        const int gn  = g + W;
        const int gnc = (gn < GROUPS4) ? gn : gw;
        const int e0n = 4 * gnc;
        const int bn  = (e0n >= NE) ? 1 : 0;
        const int ebn = e0n - bn * NE;
        const int4 gA_n = gi4[(size_t)bn * NE + ebn];
        const int4 gB_n = gi4[(size_t)bn * NE + ebn + 1];

        const __half* __restrict__ base =
            g_xti + (size_t)b * NE * TWOC + lane * 8;

        float res[12];
        do_pair(base, eb,     gA, gB, Vp, res);
        do_pair(base, eb + 2, gC, gD, Vp, res + 6);

        // single deferred butterfly: 12 parallel chains x 5 rounds
#pragma unroll
        for (int off = 16; off; off >>= 1)
#pragma unroll
            for (int r = 0; r < 12; r++)
                res[r] += __shfl_xor_sync(0xffffffffu, res[r], off);

        if (lane < 12) {
            const int u = lane / 3;
            const int k = lane - 3 * u;
            out[((size_t)b * 3 + k) * NE + eb + u] = res[lane] + cbk;
        }

        g  = gn;
        b  = bn;
        eb = ebn;
        gA = gA_n;
        gB = gB_n;
    }
}

// ---------------------------------------------------------------------------
extern "C" void kernel_launch(void* const* d_in, const int* in_sizes, int n_in,
                              void* d_out, int out_size)
{
    const float* x_0      = (const float*)d_in[0];
    const float* x_1      = (const float*)d_in[1];
    const int*   gemm     = (const int*)  d_in[2];
    const float* Wa_local = (const float*)d_in[3];
    const float* ba_local = (const float*)d_in[4];
    const float* Wb_local = (const float*)d_in[5];
    const float* bb_local = (const float*)d_in[6];
    const float* Wa_tri   = (const float*)d_in[7];
    const float* ba_tri   = (const float*)d_in[8];
    const float* Wb_tri   = (const float*)d_in[9];
    const float* bb_tri   = (const float*)d_in[10];
    const float* Wa_fuse  = (const float*)d_in[11];
    const float* ba_fuse  = (const float*)d_in[12];
    const float* Wb_fuse  = (const float*)d_in[13];
    const float* bb_fuse  = (const float*)d_in[14];
    float* out = (float*)d_out;

    prep_kernel<<<TR_BLOCKS + W_BLOCKS, 256>>>(
        x_0, x_1,
        Wa_local, ba_local, Wb_local, bb_local,
        Wa_tri, ba_tri, Wb_tri, bb_tri,
        Wa_fuse, ba_fuse, Wb_fuse, bb_fuse);

    mesh_main_kernel<<<296, 256>>>(gemm, out);
}